// round 3
// baseline (speedup 1.0000x reference)
#include <cuda_runtime.h>
#include <cuda_fp16.h>

// Problem shapes are fixed by the dataset.
#define NPOI   50000
#define NNODES 100000   // < 2^17, so node id fits 17 bits
#define NEDGES 1000000
#define NDIST  512      // dist id fits 9 bits
#define DD     64
#define SLOTS  80       // per-node incidence bucket; degree ~ Poisson(20)

// Record encoding (4 bytes):
//   bit 31      : 1 = backward record (weight = exp(adst[agg_node]), uniform)
//   bits 17..25 : dist index k (forward records only)
//   bits 0..16  : neighbor node id
#define NBR_MASK 0x1FFFFu
#define BWD_FLAG 0x80000000u

// Scratch (__device__ globals; no dynamic allocation allowed).
__device__ __half2 g_xh[NNODES * 32];   // node features, fp16 (12.8MB)
__device__ float  g_ea[NNODES];         // exp(asrc[n])
__device__ float  g_eb[NNODES];         // exp(adst[n])
__device__ int    g_cnt[NNODES];        // per-node incidence cursors
__device__ float  g_w[2 * DD];          // w_src | w_dst
__device__ float  g_expb[NDIST];        // exp(delta_dis_embs[k] . w_src)
__device__ unsigned g_adj[NNODES * SLOTS]; // packed records (32MB)

// ---------------------------------------------------------------------------
// K0: w_src = alpha_src @ W, w_dst = alpha_dst @ W, expb[k] = exp(dis[k].w_src)
// ---------------------------------------------------------------------------
__global__ void k0_precompute(const float* __restrict__ W,
                              const float* __restrict__ asw,
                              const float* __restrict__ adw,
                              const float* __restrict__ dis) {
    __shared__ float ws[DD];
    int t = threadIdx.x;
    if (t < DD) {
        float s1 = 0.f, s2 = 0.f;
        #pragma unroll 8
        for (int f = 0; f < DD; f++) {
            float w = W[f * DD + t];
            s1 += asw[f] * w;
            s2 += adw[f] * w;
        }
        ws[t] = s1;
        g_w[t] = s1;
        g_w[DD + t] = s2;
    }
    __syncthreads();
    for (int k = t; k < NDIST; k += blockDim.x) {
        const float* row = dis + k * DD;
        float s = 0.f;
        #pragma unroll 8
        for (int d = 0; d < DD; d++) s += row[d] * ws[d];
        g_expb[k] = __expf(s);
    }
}

// ---------------------------------------------------------------------------
// K1: per node n: gather POI row, store fp16; dot vs w_src/w_dst -> exp;
// zero cursor. 16 threads per node, one float4 column chunk per lane.
// ---------------------------------------------------------------------------
__global__ void k1_nodes(const float* __restrict__ poi,
                         const int* __restrict__ sess) {
    int gt = blockIdx.x * blockDim.x + threadIdx.x;
    int n = gt >> 4;
    int c = gt & 15;
    if (n >= NNODES) return;

    int p = sess[n];
    float4 v = ((const float4*)poi)[(size_t)p * 16 + c];

    __half2 h0 = __floats2half2_rn(v.x, v.y);
    __half2 h1 = __floats2half2_rn(v.z, v.w);
    uint2 pk = make_uint2(*(const unsigned*)&h0, *(const unsigned*)&h1);
    ((uint2*)g_xh)[(size_t)n * 16 + c] = pk;

    const float4* w4 = (const float4*)g_w;
    float4 a = w4[c];
    float4 d = w4[16 + c];
    float rs = v.x * a.x + v.y * a.y + v.z * a.z + v.w * a.w;
    float rd = v.x * d.x + v.y * d.y + v.z * d.z + v.w * d.w;
    #pragma unroll
    for (int o = 8; o >= 1; o >>= 1) {
        rs += __shfl_down_sync(0xffffffffu, rs, o, 16);
        rd += __shfl_down_sync(0xffffffffu, rd, o, 16);
    }
    if (c == 0) {
        g_ea[n]  = __expf(rs);
        g_eb[n]  = __expf(rd);
        g_cnt[n] = 0;
    }
}

// ---------------------------------------------------------------------------
// K2: per edge, append packed incidence records (no float math, no float
// atomics — softmax denominators are reconstructed in K3).
//   at t (fwd): neighbor s, dist k  -> weight exp(asrc[t]) * expb[k]
//   at s (bwd): neighbor t          -> weight exp(adst[s])
// ---------------------------------------------------------------------------
__global__ void k2_build(const int* __restrict__ esrc,
                         const int* __restrict__ edst,
                         const int* __restrict__ edist) {
    int e = blockIdx.x * blockDim.x + threadIdx.x;
    if (e >= NEDGES) return;
    unsigned s = esrc[e];
    unsigned t = edst[e];
    unsigned k = edist[e];
    int p1 = atomicAdd(&g_cnt[t], 1);
    if (p1 < SLOTS) g_adj[t * SLOTS + p1] = s | (k << 17);
    int p2 = atomicAdd(&g_cnt[s], 1);
    if (p2 < SLOTS) g_adj[s * SLOTS + p2] = t | BWD_FLAG;
}

// ---------------------------------------------------------------------------
// K3: warp-per-node aggregation. Two half-warps keep two records in flight;
// lane c owns 4 columns (one 8B fp16 load per record). Weights decoded from
// the record + per-node constants; denominator summed on the fly. Output
// written once, coalesced, normalized. No atomics, fp32 accumulation.
// ---------------------------------------------------------------------------
__global__ void k3_agg(float* __restrict__ out) {
    __shared__ float sh_expb[NDIST];
    for (int i = threadIdx.x; i < NDIST; i += blockDim.x)
        sh_expb[i] = g_expb[i];
    __syncthreads();

    int w = (blockIdx.x * blockDim.x + threadIdx.x) >> 5;
    if (w >= NNODES) return;
    int lane = threadIdx.x & 31;
    int c = lane & 15;
    int h = lane >> 4;

    int deg = g_cnt[w];
    if (deg > SLOTS) deg = SLOTS;
    const unsigned* adj = g_adj + (size_t)w * SLOTS;
    float ea = g_ea[w];
    float eb = g_eb[w];

    float4 acc = make_float4(0.f, 0.f, 0.f, 0.f);
    float  ssum = 0.f;
    for (int i = h; i < deg; i += 2) {
        unsigned r = adj[i];
        unsigned nbr = r & NBR_MASK;
        float wt = (r & BWD_FLAG) ? eb : ea * sh_expb[(r >> 17) & 0x1FF];
        ssum += wt;
        uint2 pk = ((const uint2*)g_xh)[(size_t)nbr * 16 + c];
        float2 f0 = __half22float2(*(const __half2*)&pk.x);
        float2 f1 = __half22float2(*(const __half2*)&pk.y);
        acc.x += wt * f0.x;
        acc.y += wt * f0.y;
        acc.z += wt * f1.x;
        acc.w += wt * f1.y;
    }
    // combine the two half-warp partials (columns align: lane c and lane c+16)
    acc.x += __shfl_down_sync(0xffffffffu, acc.x, 16);
    acc.y += __shfl_down_sync(0xffffffffu, acc.y, 16);
    acc.z += __shfl_down_sync(0xffffffffu, acc.z, 16);
    acc.w += __shfl_down_sync(0xffffffffu, acc.w, 16);
    ssum  += __shfl_down_sync(0xffffffffu, ssum, 16);

    if (h == 0) {
        float inv = 1.f / (ssum + 1e-16f);
        acc.x *= inv; acc.y *= inv; acc.z *= inv; acc.w *= inv;
        ((float4*)out)[(size_t)w * 16 + c] = acc;
    }
}

// ---------------------------------------------------------------------------
extern "C" void kernel_launch(void* const* d_in, const int* in_sizes, int n_in,
                              void* d_out, int out_size) {
    const float* poi   = (const float*)d_in[0];  // [NPOI, D]
    const float* dis   = (const float*)d_in[1];  // [NDIST, D]
    const float* W     = (const float*)d_in[2];  // [D, D]
    const float* asw   = (const float*)d_in[3];  // [D]
    const float* adw   = (const float*)d_in[4];  // [D]
    const int*   sess  = (const int*)d_in[5];    // [NNODES]
    const int*   ei    = (const int*)d_in[6];    // [2, NEDGES]
    const int*   edist = (const int*)d_in[7];    // [NEDGES]
    float* out = (float*)d_out;                  // [NNODES, D]

    const int* esrc = ei;
    const int* edst = ei + NEDGES;

    k0_precompute<<<1, 256>>>(W, asw, adw, dis);
    k1_nodes<<<(NNODES * 16 + 255) / 256, 256>>>(poi, sess);
    k2_build<<<(NEDGES + 255) / 256, 256>>>(esrc, edst, edist);
    k3_agg<<<(NNODES * 32 + 255) / 256, 256>>>(out);
}

// round 4
// speedup vs baseline: 1.5299x; 1.5299x over previous
#include <cuda_runtime.h>
#include <cuda_bf16.h>

// Problem shapes are fixed by the dataset.
#define NPOI   50000
#define NNODES 100000
#define NEDGES 1000000
#define NDIST  512
#define DD     64
#define SLOTS  80   // per-node incidence bucket; degree ~ Poisson(20), P(>80) ~ 0

// Scratch (__device__ globals; no dynamic allocation allowed).
__device__ float g_x[NNODES * DD];      // gathered node features, f32 (25.6MB)
__device__ float g_asrc[NNODES];        // x[n] . w_src
__device__ float g_adst[NNODES];        // x[n] . w_dst
__device__ int   g_cnt[NNODES];         // per-node incidence cursors
__device__ float g_w[2 * DD];           // w_src | w_dst
__device__ float g_b[NDIST];            // delta_dis_embs[k] . w_src
__device__ int2  g_adj[NNODES * SLOTS]; // {neighbor, bits(exp_weight)} (64MB)

// ---------------------------------------------------------------------------
// K0: w_src = alpha_src @ W, w_dst = alpha_dst @ W, b[k] = dis[k] . w_src
// ---------------------------------------------------------------------------
__global__ void k0_precompute(const float* __restrict__ W,
                              const float* __restrict__ asw,
                              const float* __restrict__ adw,
                              const float* __restrict__ dis) {
    __shared__ float ws[DD];
    int t = threadIdx.x;
    if (t < DD) {
        float s1 = 0.f, s2 = 0.f;
        #pragma unroll 8
        for (int f = 0; f < DD; f++) {
            float w = W[f * DD + t];
            s1 += asw[f] * w;
            s2 += adw[f] * w;
        }
        ws[t] = s1;
        g_w[t] = s1;
        g_w[DD + t] = s2;
    }
    __syncthreads();
    for (int k = t; k < NDIST; k += blockDim.x) {
        const float* row = dis + k * DD;
        float s = 0.f;
        #pragma unroll 8
        for (int d = 0; d < DD; d++) s += row[d] * ws[d];
        g_b[k] = s;
    }
}

// ---------------------------------------------------------------------------
// K1: per node n: x[n] = POI[sess[n]] (f32); a_src/a_dst dots; zero cursor.
// 16 threads per node, one float4 per lane.
// ---------------------------------------------------------------------------
__global__ void k1_nodes(const float* __restrict__ poi,
                         const int* __restrict__ sess) {
    int gt = blockIdx.x * blockDim.x + threadIdx.x;
    int n = gt >> 4;
    int c = gt & 15;
    if (n >= NNODES) return;

    int p = sess[n];
    float4 v = ((const float4*)poi)[(size_t)p * 16 + c];
    ((float4*)g_x)[(size_t)n * 16 + c] = v;

    const float4* w4 = (const float4*)g_w;
    float4 a = w4[c];
    float4 d = w4[16 + c];
    float rs = v.x * a.x + v.y * a.y + v.z * a.z + v.w * a.w;
    float rd = v.x * d.x + v.y * d.y + v.z * d.z + v.w * d.w;
    #pragma unroll
    for (int o = 8; o >= 1; o >>= 1) {
        rs += __shfl_down_sync(0xffffffffu, rs, o, 16);
        rd += __shfl_down_sync(0xffffffffu, rd, o, 16);
    }
    if (c == 0) {
        g_asrc[n] = rs;
        g_adst[n] = rd;
        g_cnt[n]  = 0;
    }
}

// ---------------------------------------------------------------------------
// K2: per edge: exp scores -> append {neighbor, weight} incidence records for
// both directions. No float atomics: K3 rebuilds the softmax denominator by
// summing record weights. Max-subtraction omitted (scores ~ N(0,2), softmax
// is shift-invariant; f32 exp is safe).
// ---------------------------------------------------------------------------
__global__ void k2_build(const int* __restrict__ esrc,
                         const int* __restrict__ edst,
                         const int* __restrict__ edist) {
    int e = blockIdx.x * blockDim.x + threadIdx.x;
    if (e >= NEDGES) return;
    int s = esrc[e];
    int t = edst[e];
    int k = edist[e];
    float ef = __expf(__ldg(&g_asrc[t]) + __ldg(&g_b[k]));
    float eb = __expf(__ldg(&g_adst[s]));
    int p1 = atomicAdd(&g_cnt[t], 1);
    if (p1 < SLOTS) g_adj[t * SLOTS + p1] = make_int2(s, __float_as_int(ef));
    int p2 = atomicAdd(&g_cnt[s], 1);
    if (p2 < SLOTS) g_adj[s * SLOTS + p2] = make_int2(t, __float_as_int(eb));
}

// ---------------------------------------------------------------------------
// K3: warp-per-node aggregation. Two half-warps; each half-warp batches FOUR
// records per iteration -> 8 independent L2 gathers in flight per warp (MLP).
// f32 accumulate; denominator summed from record weights; one coalesced
// normalized store. No atomics.
// ---------------------------------------------------------------------------
__global__ void k3_agg(float* __restrict__ out) {
    int w = (blockIdx.x * blockDim.x + threadIdx.x) >> 5;
    if (w >= NNODES) return;
    int lane = threadIdx.x & 31;
    int c = lane & 15;
    int h = lane >> 4;

    int deg = g_cnt[w];
    if (deg > SLOTS) deg = SLOTS;
    const int2* adj = g_adj + (size_t)w * SLOTS;
    const float4* x4 = (const float4*)g_x;

    float4 acc = make_float4(0.f, 0.f, 0.f, 0.f);
    float  ssum = 0.f;

    int i = h;
    // batched: 4 records per half-warp per iteration (stride 8 over the list)
    for (; i + 6 < deg; i += 8) {
        int2 r0 = __ldg(&adj[i]);
        int2 r1 = __ldg(&adj[i + 2]);
        int2 r2 = __ldg(&adj[i + 4]);
        int2 r3 = __ldg(&adj[i + 6]);
        float4 v0 = __ldg(&x4[(size_t)r0.x * 16 + c]);
        float4 v1 = __ldg(&x4[(size_t)r1.x * 16 + c]);
        float4 v2 = __ldg(&x4[(size_t)r2.x * 16 + c]);
        float4 v3 = __ldg(&x4[(size_t)r3.x * 16 + c]);
        float w0 = __int_as_float(r0.y);
        float w1 = __int_as_float(r1.y);
        float w2 = __int_as_float(r2.y);
        float w3 = __int_as_float(r3.y);
        ssum += (w0 + w1) + (w2 + w3);
        acc.x += w0 * v0.x + w1 * v1.x + w2 * v2.x + w3 * v3.x;
        acc.y += w0 * v0.y + w1 * v1.y + w2 * v2.y + w3 * v3.y;
        acc.z += w0 * v0.z + w1 * v1.z + w2 * v2.z + w3 * v3.z;
        acc.w += w0 * v0.w + w1 * v1.w + w2 * v2.w + w3 * v3.w;
    }
    // tail
    for (; i < deg; i += 2) {
        int2 r = __ldg(&adj[i]);
        float wt = __int_as_float(r.y);
        float4 v = __ldg(&x4[(size_t)r.x * 16 + c]);
        ssum  += wt;
        acc.x += wt * v.x;
        acc.y += wt * v.y;
        acc.z += wt * v.z;
        acc.w += wt * v.w;
    }

    // combine the two half-warp partials (columns align: lane c and lane c+16)
    acc.x += __shfl_down_sync(0xffffffffu, acc.x, 16);
    acc.y += __shfl_down_sync(0xffffffffu, acc.y, 16);
    acc.z += __shfl_down_sync(0xffffffffu, acc.z, 16);
    acc.w += __shfl_down_sync(0xffffffffu, acc.w, 16);
    ssum  += __shfl_down_sync(0xffffffffu, ssum, 16);

    if (h == 0) {
        float inv = 1.f / (ssum + 1e-16f);
        acc.x *= inv; acc.y *= inv; acc.z *= inv; acc.w *= inv;
        ((float4*)out)[(size_t)w * 16 + c] = acc;
    }
}

// ---------------------------------------------------------------------------
extern "C" void kernel_launch(void* const* d_in, const int* in_sizes, int n_in,
                              void* d_out, int out_size) {
    const float* poi   = (const float*)d_in[0];  // [NPOI, D]
    const float* dis   = (const float*)d_in[1];  // [NDIST, D]
    const float* W     = (const float*)d_in[2];  // [D, D]
    const float* asw   = (const float*)d_in[3];  // [D]
    const float* adw   = (const float*)d_in[4];  // [D]
    const int*   sess  = (const int*)d_in[5];    // [NNODES]
    const int*   ei    = (const int*)d_in[6];    // [2, NEDGES]
    const int*   edist = (const int*)d_in[7];    // [NEDGES]
    float* out = (float*)d_out;                  // [NNODES, D]

    const int* esrc = ei;
    const int* edst = ei + NEDGES;

    k0_precompute<<<1, 256>>>(W, asw, adw, dis);
    k1_nodes<<<(NNODES * 16 + 255) / 256, 256>>>(poi, sess);
    k2_build<<<(NEDGES + 255) / 256, 256>>>(esrc, edst, edist);
    k3_agg<<<(NNODES * 32 + 255) / 256, 256>>>(out);
}